// round 7
// baseline (speedup 1.0000x reference)
#include <cuda_runtime.h>
#include <cuda_bf16.h>
#include <cstdint>

#define Bb 2
#define Ss 2048
#define Dd 512
#define Hh 8
#define HDIM 64
#define SCALE 0.125f

// ---------------------------------------------------------------------------
// Device-global scratch (no allocation allowed)
// ---------------------------------------------------------------------------
__device__ uint16_t g_gene_h[Bb*Ss*Dd], g_gene_l[Bb*Ss*Dd];
__device__ uint16_t g_expr_h[Bb*Ss*Dd], g_expr_l[Bb*Ss*Dd];
__device__ uint16_t g_fus_h[Bb*Ss*Dd],  g_fus_l[Bb*Ss*Dd];
__device__ uint16_t g_q_h[Bb*Ss*Dd],    g_q_l[Bb*Ss*Dd];
__device__ uint16_t g_k_h[Bb*Ss*Dd],    g_k_l[Bb*Ss*Dd];
__device__ uint16_t g_v_h[Bb*Ss*Dd],    g_v_l[Bb*Ss*Dd];
__device__ uint16_t g_at_h[Bb*Ss*Dd],   g_at_l[Bb*Ss*Dd];
// transposed weights [N][K] hi/lo planes
__device__ uint16_t g_wtf_h[Dd*2*Dd],   g_wtf_l[Dd*2*Dd];       // [512][1024]
__device__ uint16_t g_wtqk_h[2*Dd*Dd],  g_wtqk_l[2*Dd*Dd];      // [1024][512] (Q rows then K rows)
__device__ uint16_t g_wtv_h[Dd*Dd], g_wtv_l[Dd*Dd];
__device__ uint16_t g_wto_h[Dd*Dd], g_wto_l[Dd*Dd];
__device__ uint32_t g_mbits[Bb*Ss*(Ss/32)];

// ---------------------------------------------------------------------------
// Helpers
// ---------------------------------------------------------------------------
__device__ __forceinline__ uint32_t smem_u32(const void* p) {
    return (uint32_t)__cvta_generic_to_shared(p);
}
__device__ __forceinline__ void split2(float x, float y, uint32_t &hi, uint32_t &lo) {
    __nv_bfloat162 h = __floats2bfloat162_rn(x, y);
    float2 hf = __bfloat1622float2(h);
    __nv_bfloat162 l = __floats2bfloat162_rn(x - hf.x, y - hf.y);
    hi = reinterpret_cast<uint32_t&>(h);
    lo = reinterpret_cast<uint32_t&>(l);
}
__device__ __forceinline__ void mma16816(float c[4], const uint32_t* a, const uint32_t* b) {
    asm volatile(
        "mma.sync.aligned.m16n8k16.row.col.f32.bf16.bf16.f32 "
        "{%0,%1,%2,%3}, {%4,%5,%6,%7}, {%8,%9}, {%0,%1,%2,%3};\n"
        : "+f"(c[0]), "+f"(c[1]), "+f"(c[2]), "+f"(c[3])
        : "r"(a[0]), "r"(a[1]), "r"(a[2]), "r"(a[3]), "r"(b[0]), "r"(b[1]));
}
__device__ __forceinline__ void ldsm_x4(uint32_t a[4], uint32_t addr) {
    asm volatile("ldmatrix.sync.aligned.m8n8.x4.shared.b16 {%0,%1,%2,%3}, [%4];"
        : "=r"(a[0]), "=r"(a[1]), "=r"(a[2]), "=r"(a[3]) : "r"(addr));
}
__device__ __forceinline__ void ldsm_x4_t(uint32_t a[4], uint32_t addr) {
    asm volatile("ldmatrix.sync.aligned.m8n8.x4.trans.shared.b16 {%0,%1,%2,%3}, [%4];"
        : "=r"(a[0]), "=r"(a[1]), "=r"(a[2]), "=r"(a[3]) : "r"(addr));
}
__device__ __forceinline__ void cpa16(uint32_t dst, const void* src) {
    asm volatile("cp.async.cg.shared.global [%0], [%1], 16;" :: "r"(dst), "l"(src));
}
__device__ __forceinline__ void cpa_commit() { asm volatile("cp.async.commit_group;"); }
template<int N> __device__ __forceinline__ void cpa_wait() {
    asm volatile("cp.async.wait_group %0;" :: "n"(N) : "memory");
}

// ---------------------------------------------------------------------------
// Pre-pass kernels
// ---------------------------------------------------------------------------
__global__ __launch_bounds__(256) void maskbits_kernel(const float* __restrict__ M,
                                                       uint32_t* __restrict__ bits) {
    int idx = blockIdx.x * 256 + threadIdx.x;
    float v = M[idx];
    uint32_t b = __ballot_sync(0xffffffffu, v != 0.f);
    if ((threadIdx.x & 31) == 0) bits[idx >> 5] = b;
}

__global__ __launch_bounds__(256) void split_kernel(const float* __restrict__ in,
                                                    uint16_t* __restrict__ hi,
                                                    uint16_t* __restrict__ lo) {
    int i = (blockIdx.x * 256 + threadIdx.x) * 4;
    float4 v = *(const float4*)(in + i);
    uint32_t h0, l0, h1, l1;
    split2(v.x, v.y, h0, l0);
    split2(v.z, v.w, h1, l1);
    *(uint2*)(hi + i) = make_uint2(h0, h1);
    *(uint2*)(lo + i) = make_uint2(l0, l1);
}

// W[K][N] -> WT[N][K] hi/lo planes
__global__ __launch_bounds__(256) void transpose_split_kernel(
    const float* __restrict__ W, uint16_t* __restrict__ Th, uint16_t* __restrict__ Tl,
    int K, int N)
{
    __shared__ float t[32][33];
    int n0 = blockIdx.x * 32, k0 = blockIdx.y * 32;
    int tx = threadIdx.x & 31, ty = threadIdx.x >> 5;
    #pragma unroll
    for (int i = 0; i < 4; i++) {
        int k = k0 + ty + i * 8;
        t[ty + i * 8][tx] = W[(size_t)k * N + n0 + tx];
    }
    __syncthreads();
    #pragma unroll
    for (int i = 0; i < 4; i++) {
        int n = n0 + ty + i * 8;
        float v = t[tx][ty + i * 8];
        __nv_bfloat16 h = __float2bfloat16(v);
        __nv_bfloat16 l = __float2bfloat16(v - __bfloat162float(h));
        Th[(size_t)n * K + k0 + tx] = reinterpret_cast<uint16_t&>(h);
        Tl[(size_t)n * K + k0 + tx] = reinterpret_cast<uint16_t&>(l);
    }
}

// ---------------------------------------------------------------------------
// bf16x3 HMMA GEMM: C[4096][N] = A[4096][K] @ WT^T + bias, per-half scaling.
//   A: row-major hi/lo planes (row stride 512; switches A1->A2 at k=512).
//   B: WT [N][K] hi/lo planes (K-major rows) -> non-trans ldmatrix.
// BM=128, BN in {64,128}, BK=32. Warps 4m x 2n. cp.async pipeline.
// For merged QK (N=1024): cols >= 512 route to Ch2/Cl2 with scale 1,
// cols < 512 to Ch/Cl with scale1 (SCALE for Q).
// ---------------------------------------------------------------------------
#define GSTR 40   // smem row stride in elems (32 data + 8 pad); 80B, 16B-aligned

template<int BN>
__global__ __launch_bounds__(256) void gemm_tc(
    const uint16_t* __restrict__ A1h, const uint16_t* __restrict__ A1l,
    const uint16_t* __restrict__ A2h, const uint16_t* __restrict__ A2l,
    const uint16_t* __restrict__ Bth, const uint16_t* __restrict__ Btl,
    const float* __restrict__ bias1, const float* __restrict__ bias2,
    float* __restrict__ Cf,
    uint16_t* __restrict__ Ch,  uint16_t* __restrict__ Cl,
    uint16_t* __restrict__ Ch2, uint16_t* __restrict__ Cl2,
    int K, float scale1)
{
    constexpr int STAGES = (BN == 64) ? 3 : 2;
    constexpr int APL = 128 * GSTR;            // A plane elems
    constexpr int BPL = BN * GSTR;             // B plane elems
    constexpr int STG = 2 * APL + 2 * BPL;     // stage elems
    constexpr int WN16 = BN / 32;              // n16 groups per warp
    constexpr int NACC = BN / 16;              // n8 acc groups per warp

    extern __shared__ uint16_t sm[];
    const int tid  = threadIdx.x;
    const int lane = tid & 31, wid = tid >> 5;
    const int grp  = lane >> 2, tig = lane & 3;
    const int wm = (wid & 3) * 32, wn = (wid >> 2) * (BN / 2);
    const int rowBase = blockIdx.y * 128, colBase = blockIdx.x * BN;

    const int arow = ((lane >> 3) & 1) * 8 + (lane & 7);   // A ldsm pattern
    const int acol = (lane >> 4) * 8;
    const int brow = (lane >> 4) * 8 + (lane & 7);          // B non-trans pattern
    const int bcol = ((lane >> 3) & 1) * 8;

    float acc[2][NACC][4];
    #pragma unroll
    for (int mt = 0; mt < 2; mt++)
        #pragma unroll
        for (int nt = 0; nt < NACC; nt++)
            #pragma unroll
            for (int j = 0; j < 4; j++) acc[mt][nt][j] = 0.f;

    const int NIT = K / 32;
    const uint32_t base = smem_u32(sm);

    auto load_chunk = [&](int it) {
        uint32_t sb = base + (it % STAGES) * STG * 2;
        int k0 = it * 32;
        const uint16_t* Ah_ = (k0 < Dd) ? A1h : A2h;
        const uint16_t* Al_ = (k0 < Dd) ? A1l : A2l;
        int ka = k0 & (Dd - 1);
        // A: 128 rows x 32 elems = 512 chunks of 8 elems -> 2 per thread per plane
        #pragma unroll
        for (int i = 0; i < 2; i++) {
            int idx = tid + i * 256;
            int r = idx >> 2, ch = idx & 3;
            size_t g = (size_t)(rowBase + r) * Dd + ka + ch * 8;
            uint32_t d = (r * GSTR + ch * 8) * 2;
            cpa16(sb + d,            Ah_ + g);
            cpa16(sb + APL * 2 + d,  Al_ + g);
        }
        // B: BN rows x 32 elems
        #pragma unroll
        for (int i = 0; i < BN / 64; i++) {
            int idx = tid + i * 256;
            int r = idx >> 2, ch = idx & 3;
            size_t g = (size_t)(colBase + r) * K + k0 + ch * 8;
            uint32_t d = (2 * APL + r * GSTR + ch * 8) * 2;
            cpa16(sb + d,            Bth + g);
            cpa16(sb + BPL * 2 + d,  Btl + g);
        }
        cpa_commit();
    };

    #pragma unroll
    for (int i = 0; i < STAGES - 1; i++) load_chunk(i);

    for (int it = 0; it < NIT; it++) {
        if (STAGES == 3) {
            if (it + 1 < NIT) cpa_wait<1>(); else cpa_wait<0>();
        } else {
            cpa_wait<0>();
        }
        __syncthreads();
        if (it + STAGES - 1 < NIT) load_chunk(it + STAGES - 1);

        const uint16_t* Ah = sm + (it % STAGES) * STG;
        const uint16_t* Al = Ah + APL;
        const uint16_t* Bh = Ah + 2 * APL;
        const uint16_t* Bl = Bh + BPL;

        #pragma unroll
        for (int kk = 0; kk < 2; kk++) {
            uint32_t ah[2][4], al[2][4];
            #pragma unroll
            for (int mt = 0; mt < 2; mt++) {
                int off = (wm + mt * 16 + arow) * GSTR + kk * 16 + acol;
                ldsm_x4(ah[mt], smem_u32(&Ah[off]));
                ldsm_x4(al[mt], smem_u32(&Al[off]));
            }
            #pragma unroll
            for (int g = 0; g < WN16; g++) {
                uint32_t bh4[4], bl4[4];
                int off = (wn + g * 16 + brow) * GSTR + kk * 16 + bcol;
                ldsm_x4(bh4, smem_u32(&Bh[off]));
                ldsm_x4(bl4, smem_u32(&Bl[off]));
                #pragma unroll
                for (int mt = 0; mt < 2; mt++) {
                    mma16816(acc[mt][2*g],   ah[mt], bh4);
                    mma16816(acc[mt][2*g],   al[mt], bh4);
                    mma16816(acc[mt][2*g],   ah[mt], bl4);
                    mma16816(acc[mt][2*g+1], ah[mt], bh4 + 2);
                    mma16816(acc[mt][2*g+1], al[mt], bh4 + 2);
                    mma16816(acc[mt][2*g+1], ah[mt], bl4 + 2);
                }
            }
        }
        __syncthreads();
    }

    // Epilogue: route by column half (merged QK); f32 or hi/lo plane output.
    const bool second = (colBase >= Dd);
    const float xscale = second ? 1.f : scale1;
    const float* bias = second ? bias2 : bias1;
    uint16_t* Dh = second ? Ch2 : Ch;
    uint16_t* Dl = second ? Cl2 : Cl;
    const int colOff = second ? (colBase - Dd) : colBase;

    #pragma unroll
    for (int mt = 0; mt < 2; mt++)
        #pragma unroll
        for (int nt = 0; nt < NACC; nt++) {
            int row = rowBase + wm + mt * 16 + grp;
            int col = colOff + wn + nt * 8 + 2 * tig;
            float bx = bias[col], by = bias[col + 1];
            float v00 = (acc[mt][nt][0] + bx) * xscale;
            float v01 = (acc[mt][nt][1] + by) * xscale;
            float v10 = (acc[mt][nt][2] + bx) * xscale;
            float v11 = (acc[mt][nt][3] + by) * xscale;
            if (Cf) {
                *(float2*)(Cf + (size_t)row * Dd + col)       = make_float2(v00, v01);
                *(float2*)(Cf + (size_t)(row + 8) * Dd + col) = make_float2(v10, v11);
            } else {
                uint32_t h0, l0, h1, l1;
                split2(v00, v01, h0, l0);
                split2(v10, v11, h1, l1);
                *(uint32_t*)&Dh[(size_t)row * Dd + col]       = h0;
                *(uint32_t*)&Dl[(size_t)row * Dd + col]       = l0;
                *(uint32_t*)&Dh[(size_t)(row + 8) * Dd + col] = h1;
                *(uint32_t*)&Dl[(size_t)(row + 8) * Dd + col] = l1;
            }
        }
}

// ---------------------------------------------------------------------------
// Flash attention: bf16x3 HMMA, BQ=128 (8 warps), BK=64, 3-stage cp.async.
// Q pre-scaled by SCALE (folded into QK GEMM epilogue). Masked p zeroed, so
// running l == reference's sum|A|. Writes attn hi/lo planes.
// ---------------------------------------------------------------------------
#define FSTR 72
#define F_STAGE 18432   // elems: 4 planes * 64*72

__global__ __launch_bounds__(256) void flash_bf3_kernel(
    const uint16_t* __restrict__ Qh, const uint16_t* __restrict__ Ql,
    const uint16_t* __restrict__ Kgh, const uint16_t* __restrict__ Kgl,
    const uint16_t* __restrict__ Vgh, const uint16_t* __restrict__ Vgl,
    const uint32_t* __restrict__ mbits,
    uint16_t* __restrict__ Oh, uint16_t* __restrict__ Ol)
{
    extern __shared__ uint16_t sm[];
    const int tid = threadIdx.x, lane = tid & 31, w = tid >> 5;
    const int grp = lane >> 2, tig = lane & 3;
    const int b = blockIdx.y >> 3, h = blockIdx.y & 7;
    const int q0 = blockIdx.x * 128;

    const int arow = ((lane >> 3) & 1) * 8 + (lane & 7);
    const int acol = (lane >> 4) * 8;
    const int brow = (lane >> 4) * 8 + (lane & 7);
    const int bcol = ((lane >> 3) & 1) * 8;

    // ---- stage Q planes (128 x 64) through stage-0 buffer, pull A-frags ----
    {
        uint32_t base = smem_u32(sm);
        #pragma unroll
        for (int i = 0; i < 4; i++) {
            int chunk = tid + i * 256;
            int r = chunk >> 3, c = (chunk & 7) * 8;
            const size_t g = (size_t)(b * Ss + q0 + r) * Dd + h * HDIM + c;
            cpa16(base + (r * FSTR + c) * 2,          Qh + g);
            cpa16(base + (9216 + r * FSTR + c) * 2,   Ql + g);
        }
        cpa_commit();
        cpa_wait<0>();
        __syncthreads();
    }
    uint32_t qh[4][4], ql[4][4];
    #pragma unroll
    for (int c = 0; c < 4; c++) {
        int off = (w * 16 + arow) * FSTR + c * 16 + acol;
        ldsm_x4(qh[c], smem_u32(&sm[off]));
        ldsm_x4(ql[c], smem_u32(&sm[9216 + off]));
    }
    __syncthreads();   // all warps done reading Q before K/V loads overwrite

    float oacc[8][4];
    #pragma unroll
    for (int n = 0; n < 8; n++)
        #pragma unroll
        for (int j = 0; j < 4; j++) oacc[n][j] = 0.f;
    float mrun[2] = {-3.0e38f, -3.0e38f}, lrun[2] = {0.f, 0.f};

    auto load_tile = [&](int it) {
        int k0 = it * 64;
        uint32_t base = smem_u32(sm) + (it % 3) * F_STAGE * 2;
        #pragma unroll
        for (int i = 0; i < 2; i++) {
            int chunk = tid + i * 256;
            int r = chunk >> 3, c = (chunk & 7) * 8;
            const size_t g = (size_t)(b * Ss + k0 + r) * Dd + h * HDIM + c;
            uint32_t d = (r * FSTR + c) * 2;
            cpa16(base + d,                 Kgh + g);
            cpa16(base + 4608 * 2 + d,      Kgl + g);
            cpa16(base + 9216 * 2 + d,      Vgh + g);
            cpa16(base + 13824 * 2 + d,     Vgl + g);
        }
        cpa_commit();
    };

    load_tile(0);
    load_tile(1);

    const int NT = Ss / 64;
    for (int it = 0; it < NT; it++) {
        if (it + 1 < NT) cpa_wait<1>(); else cpa_wait<0>();
        __syncthreads();
        if (it + 2 < NT) load_tile(it + 2);

        const uint16_t* Kh = sm + (it % 3) * F_STAGE;
        const uint16_t* Kl = Kh + 4608;
        const uint16_t* Vh = Kh + 9216;
        const uint16_t* Vl = Kh + 13824;
        const int k0 = it * 64;

        // S = Qs @ K^T
        float sacc[8][4];
        #pragma unroll
        for (int n = 0; n < 8; n++)
            #pragma unroll
            for (int j = 0; j < 4; j++) sacc[n][j] = 0.f;
        #pragma unroll
        for (int g = 0; g < 4; g++)
            #pragma unroll
            for (int c = 0; c < 4; c++) {
                uint32_t kf[4], kfl[4];
                int off = (g * 16 + brow) * FSTR + c * 16 + bcol;
                ldsm_x4(kf,  smem_u32(&Kh[off]));
                ldsm_x4(kfl, smem_u32(&Kl[off]));
                mma16816(sacc[2*g],   qh[c], kf);
                mma16816(sacc[2*g],   ql[c], kf);
                mma16816(sacc[2*g],   qh[c], kfl);
                mma16816(sacc[2*g+1], qh[c], kf + 2);
                mma16816(sacc[2*g+1], ql[c], kf + 2);
                mma16816(sacc[2*g+1], qh[c], kfl + 2);
            }

        // ---- masked online softmax ----
        #pragma unroll
        for (int r = 0; r < 2; r++) {
            int qrow = q0 + w * 16 + grp + r * 8;
            size_t mb = ((size_t)(b * Ss) + qrow) * (Ss / 32) + (k0 >> 5);
            uint32_t bw0 = mbits[mb], bw1 = mbits[mb + 1];
            float tm = -3.0e38f;
            #pragma unroll
            for (int n = 0; n < 8; n++)
                #pragma unroll
                for (int e = 0; e < 2; e++) {
                    int col = n * 8 + 2 * tig + e;
                    uint32_t on = ((n < 4 ? bw0 : bw1) >> (col & 31)) & 1u;
                    float sv = on ? sacc[n][r*2+e] : -1.0e9f;
                    sacc[n][r*2+e] = sv;
                    tm = fmaxf(tm, sv);
                }
            tm = fmaxf(tm, __shfl_xor_sync(0xffffffffu, tm, 1));
            tm = fmaxf(tm, __shfl_xor_sync(0xffffffffu, tm, 2));
            float mn = fmaxf(mrun[r], tm);
            float co = __expf(mrun[r] - mn);
            float ps = 0.f;
            #pragma unroll
            for (int n = 0; n < 8; n++)
                #pragma unroll
                for (int e = 0; e < 2; e++) {
                    float sv = sacc[n][r*2+e];
                    float p = (sv == -1.0e9f) ? 0.f : __expf(sv - mn);
                    sacc[n][r*2+e] = p;
                    ps += p;
                }
            ps += __shfl_xor_sync(0xffffffffu, ps, 1);
            ps += __shfl_xor_sync(0xffffffffu, ps, 2);
            mrun[r] = mn;
            lrun[r] = lrun[r] * co + ps;
            #pragma unroll
            for (int n = 0; n < 8; n++) {
                oacc[n][r*2]   *= co;
                oacc[n][r*2+1] *= co;
            }
        }

        // ---- O += P @ V (P c-frags -> A-frags in registers) ----
        #pragma unroll
        for (int kc = 0; kc < 4; kc++) {
            uint32_t ah[4], al[4];
            split2(sacc[2*kc][0],   sacc[2*kc][1],   ah[0], al[0]);
            split2(sacc[2*kc][2],   sacc[2*kc][3],   ah[1], al[1]);
            split2(sacc[2*kc+1][0], sacc[2*kc+1][1], ah[2], al[2]);
            split2(sacc[2*kc+1][2], sacc[2*kc+1][3], ah[3], al[3]);
            #pragma unroll
            for (int c = 0; c < 4; c++) {
                uint32_t vf[4], vfl[4];
                int off = (kc * 16 + arow) * FSTR + c * 16 + acol;
                ldsm_x4_t(vf,  smem_u32(&Vh[off]));
                ldsm_x4_t(vfl, smem_u32(&Vl[off]));
                mma16816(oacc[2*c],   ah, vf);
                mma16816(oacc[2*c],   al, vf);
                mma16816(oacc[2*c],   ah, vfl);
                mma16816(oacc[2*c+1], ah, vf + 2);
                mma16816(oacc[2*c+1], al, vf + 2);
                mma16816(oacc[2*c+1], ah, vfl + 2);
            }
        }
    }

    // ---- epilogue ----
    float inv0 = (lrun[0] > 0.f) ? 1.f / lrun[0] : 0.f;
    float inv1 = (lrun[1] > 0.f) ? 1.f / lrun[1] : 0.f;
    int row0 = b * Ss + q0 + w * 16 + grp;
    #pragma unroll
    for (int n = 0; n < 8; n++) {
        int col = h * HDIM + n * 8 + 2 * tig;
        uint32_t h0, l0, h1, l1;
        split2(oacc[n][0] * inv0, oacc[n][1] * inv0, h0, l0);
        split2(oacc[n][2] * inv1, oacc[n][3] * inv1, h1, l1);
        *(uint32_t*)&Oh[(size_t)row0 * Dd + col]       = h0;
        *(uint32_t*)&Ol[(size_t)row0 * Dd + col]       = l0;
        *(uint32_t*)&Oh[(size_t)(row0 + 8) * Dd + col] = h1;
        *(uint32_t*)&Ol[(size_t)(row0 + 8) * Dd + col] = l1;
    }
}

// ---------------------------------------------------------------------------
extern "C" void kernel_launch(void* const* d_in, const int* in_sizes, int n_in,
                              void* d_out, int out_size)
{
    const float* gene = (const float*)d_in[0];
    const float* expr = (const float*)d_in[1];
    const float* Mm   = (const float*)d_in[2];
    const float* Wf   = (const float*)d_in[3];
    const float* bf   = (const float*)d_in[4];
    const float* Wq   = (const float*)d_in[5];
    const float* bq   = (const float*)d_in[6];
    const float* Wk   = (const float*)d_in[7];
    const float* bk   = (const float*)d_in[8];
    const float* Wv   = (const float*)d_in[9];
    const float* bv   = (const float*)d_in[10];
    const float* Wo   = (const float*)d_in[11];
    const float* bo   = (const float*)d_in[12];
    float* out = (float*)d_out;

    uint16_t *geneh, *genel, *exprh, *exprl, *fush, *fusl;
    uint16_t *qh, *ql, *kh, *kl, *vh, *vl, *ath, *atl;
    uint16_t *wtfh, *wtfl, *wtqkh, *wtqkl, *wtvh, *wtvl, *wtoh, *wtol;
    uint32_t* mbits;
    cudaGetSymbolAddress((void**)&geneh, g_gene_h); cudaGetSymbolAddress((void**)&genel, g_gene_l);
    cudaGetSymbolAddress((void**)&exprh, g_expr_h); cudaGetSymbolAddress((void**)&exprl, g_expr_l);
    cudaGetSymbolAddress((void**)&fush,  g_fus_h);  cudaGetSymbolAddress((void**)&fusl,  g_fus_l);
    cudaGetSymbolAddress((void**)&qh,    g_q_h);    cudaGetSymbolAddress((void**)&ql,    g_q_l);
    cudaGetSymbolAddress((void**)&kh,    g_k_h);    cudaGetSymbolAddress((void**)&kl,    g_k_l);
    cudaGetSymbolAddress((void**)&vh,    g_v_h);    cudaGetSymbolAddress((void**)&vl,    g_v_l);
    cudaGetSymbolAddress((void**)&ath,   g_at_h);   cudaGetSymbolAddress((void**)&atl,   g_at_l);
    cudaGetSymbolAddress((void**)&wtfh,  g_wtf_h);  cudaGetSymbolAddress((void**)&wtfl,  g_wtf_l);
    cudaGetSymbolAddress((void**)&wtqkh, g_wtqk_h); cudaGetSymbolAddress((void**)&wtqkl, g_wtqk_l);
    cudaGetSymbolAddress((void**)&wtvh,  g_wtv_h);  cudaGetSymbolAddress((void**)&wtvl,  g_wtv_l);
    cudaGetSymbolAddress((void**)&wtoh,  g_wto_h);  cudaGetSymbolAddress((void**)&wtol,  g_wto_l);
    cudaGetSymbolAddress((void**)&mbits, g_mbits);

    // dynamic smem: BN64 -> 3 stages, BN128 -> 2 stages
    const int SM64  = 3 * (2 * 128 * GSTR + 2 * 64 * GSTR) * 2;    // 92160 B
    const int SM128 = 2 * (2 * 128 * GSTR + 2 * 128 * GSTR) * 2;   // 81920 B
    const int SMF   = 3 * F_STAGE * 2;                             // 110592 B
    cudaFuncSetAttribute(gemm_tc<64>,  cudaFuncAttributeMaxDynamicSharedMemorySize, SM64);
    cudaFuncSetAttribute(gemm_tc<128>, cudaFuncAttributeMaxDynamicSharedMemorySize, SM128);
    cudaFuncSetAttribute(flash_bf3_kernel, cudaFuncAttributeMaxDynamicSharedMemorySize, SMF);

    const int NE = Bb * Ss * Dd;
    maskbits_kernel<<<(Bb * Ss * Ss) / 256, 256>>>(Mm, mbits);
    split_kernel<<<NE / 1024, 256>>>(gene, geneh, genel);
    split_kernel<<<NE / 1024, 256>>>(expr, exprh, exprl);
    transpose_split_kernel<<<dim3(Dd / 32, (2 * Dd) / 32), 256>>>(Wf, wtfh, wtfl, 2 * Dd, Dd);
    transpose_split_kernel<<<dim3(Dd / 32, Dd / 32), 256>>>(Wq, wtqkh, wtqkl, Dd, Dd);
    transpose_split_kernel<<<dim3(Dd / 32, Dd / 32), 256>>>(Wk, wtqkh + (size_t)Dd * Dd,
                                                            wtqkl + (size_t)Dd * Dd, Dd, Dd);
    transpose_split_kernel<<<dim3(Dd / 32, Dd / 32), 256>>>(Wv, wtvh, wtvl, Dd, Dd);
    transpose_split_kernel<<<dim3(Dd / 32, Dd / 32), 256>>>(Wo, wtoh, wtol, Dd, Dd);

    const int MR = Bb * Ss;                       // 4096
    // fused = [gene; expr] @ Wf + bf  (K=1024)
    gemm_tc<64><<<dim3(Dd / 64, MR / 128), 256, SM64>>>(
        geneh, genel, exprh, exprl, wtfh, wtfl, bf, bf,
        nullptr, fush, fusl, nullptr, nullptr, 2 * Dd, 1.f);
    // merged QK: N=1024; first half -> Q (x SCALE), second half -> K
    gemm_tc<128><<<dim3((2 * Dd) / 128, MR / 128), 256, SM128>>>(
        fush, fusl, fush, fusl, wtqkh, wtqkl, bq, bk,
        nullptr, qh, ql, kh, kl, Dd, SCALE);
    gemm_tc<64><<<dim3(Dd / 64, MR / 128), 256, SM64>>>(
        exprh, exprl, exprh, exprl, wtvh, wtvl, bv, bv,
        nullptr, vh, vl, nullptr, nullptr, Dd, 1.f);

    flash_bf3_kernel<<<dim3(Ss / 128, Bb * Hh), 256, SMF>>>(
        qh, ql, kh, kl, vh, vl, mbits, ath, atl);

    gemm_tc<64><<<dim3(Dd / 64, MR / 128), 256, SM64>>>(
        ath, atl, ath, atl, wtoh, wtol, bo, bo,
        out, nullptr, nullptr, nullptr, nullptr, Dd, 1.f);
}

// round 8
// speedup vs baseline: 1.0153x; 1.0153x over previous
#include <cuda_runtime.h>
#include <cuda_bf16.h>
#include <cstdint>

#define Bb 2
#define Ss 2048
#define Dd 512
#define Hh 8
#define HDIM 64
#define SCALE 0.125f

// ---------------------------------------------------------------------------
// Device-global scratch
// ---------------------------------------------------------------------------
__device__ uint16_t g_gene_h[Bb*Ss*Dd], g_gene_l[Bb*Ss*Dd];
__device__ uint16_t g_expr_h[Bb*Ss*Dd], g_expr_l[Bb*Ss*Dd];
__device__ uint16_t g_fus_h[Bb*Ss*Dd],  g_fus_l[Bb*Ss*Dd];
__device__ uint16_t g_q_h[Bb*Ss*Dd],    g_q_l[Bb*Ss*Dd];
__device__ uint16_t g_k_h[Bb*Ss*Dd],    g_k_l[Bb*Ss*Dd];
__device__ uint16_t g_v_h[Bb*Ss*Dd],    g_v_l[Bb*Ss*Dd];
__device__ uint16_t g_at_h[Bb*Ss*Dd],   g_at_l[Bb*Ss*Dd];
__device__ uint16_t g_wtf_h[Dd*2*Dd],   g_wtf_l[Dd*2*Dd];       // [512][1024]
__device__ uint16_t g_wtqk_h[2*Dd*Dd],  g_wtqk_l[2*Dd*Dd];      // [1024][512]
__device__ uint16_t g_wtv_h[Dd*Dd], g_wtv_l[Dd*Dd];
__device__ uint16_t g_wto_h[Dd*Dd], g_wto_l[Dd*Dd];
__device__ uint32_t g_mbits[Bb*Ss*(Ss/32)];

// ---------------------------------------------------------------------------
// Helpers
// ---------------------------------------------------------------------------
__device__ __forceinline__ uint32_t smem_u32(const void* p) {
    return (uint32_t)__cvta_generic_to_shared(p);
}
__device__ __forceinline__ void split2(float x, float y, uint32_t &hi, uint32_t &lo) {
    __nv_bfloat162 h = __floats2bfloat162_rn(x, y);
    float2 hf = __bfloat1622float2(h);
    __nv_bfloat162 l = __floats2bfloat162_rn(x - hf.x, y - hf.y);
    hi = reinterpret_cast<uint32_t&>(h);
    lo = reinterpret_cast<uint32_t&>(l);
}
__device__ __forceinline__ void mma16816(float c[4], const uint32_t* a, const uint32_t* b) {
    asm volatile(
        "mma.sync.aligned.m16n8k16.row.col.f32.bf16.bf16.f32 "
        "{%0,%1,%2,%3}, {%4,%5,%6,%7}, {%8,%9}, {%0,%1,%2,%3};\n"
        : "+f"(c[0]), "+f"(c[1]), "+f"(c[2]), "+f"(c[3])
        : "r"(a[0]), "r"(a[1]), "r"(a[2]), "r"(a[3]), "r"(b[0]), "r"(b[1]));
}
__device__ __forceinline__ void ldsm_x4(uint32_t a[4], uint32_t addr) {
    asm volatile("ldmatrix.sync.aligned.m8n8.x4.shared.b16 {%0,%1,%2,%3}, [%4];"
        : "=r"(a[0]), "=r"(a[1]), "=r"(a[2]), "=r"(a[3]) : "r"(addr));
}
__device__ __forceinline__ void ldsm_x4_t(uint32_t a[4], uint32_t addr) {
    asm volatile("ldmatrix.sync.aligned.m8n8.x4.trans.shared.b16 {%0,%1,%2,%3}, [%4];"
        : "=r"(a[0]), "=r"(a[1]), "=r"(a[2]), "=r"(a[3]) : "r"(addr));
}
__device__ __forceinline__ void cpa16(uint32_t dst, const void* src) {
    asm volatile("cp.async.cg.shared.global [%0], [%1], 16;" :: "r"(dst), "l"(src));
}
__device__ __forceinline__ void cpa_commit() { asm volatile("cp.async.commit_group;"); }
template<int N> __device__ __forceinline__ void cpa_wait() {
    asm volatile("cp.async.wait_group %0;" :: "n"(N) : "memory");
}

// ---------------------------------------------------------------------------
// Pre-pass kernels
// ---------------------------------------------------------------------------
__global__ __launch_bounds__(256) void maskbits_kernel(const float* __restrict__ M,
                                                       uint32_t* __restrict__ bits) {
    int idx = blockIdx.x * 256 + threadIdx.x;
    float v = M[idx];
    uint32_t b = __ballot_sync(0xffffffffu, v != 0.f);
    if ((threadIdx.x & 31) == 0) bits[idx >> 5] = b;
}

__global__ __launch_bounds__(256) void split_kernel(const float* __restrict__ in,
                                                    uint16_t* __restrict__ hi,
                                                    uint16_t* __restrict__ lo) {
    int i = (blockIdx.x * 256 + threadIdx.x) * 4;
    float4 v = *(const float4*)(in + i);
    uint32_t h0, l0, h1, l1;
    split2(v.x, v.y, h0, l0);
    split2(v.z, v.w, h1, l1);
    *(uint2*)(hi + i) = make_uint2(h0, h1);
    *(uint2*)(lo + i) = make_uint2(l0, l1);
}

__global__ __launch_bounds__(256) void transpose_split_kernel(
    const float* __restrict__ W, uint16_t* __restrict__ Th, uint16_t* __restrict__ Tl,
    int K, int N)
{
    __shared__ float t[32][33];
    int n0 = blockIdx.x * 32, k0 = blockIdx.y * 32;
    int tx = threadIdx.x & 31, ty = threadIdx.x >> 5;
    #pragma unroll
    for (int i = 0; i < 4; i++) {
        int k = k0 + ty + i * 8;
        t[ty + i * 8][tx] = W[(size_t)k * N + n0 + tx];
    }
    __syncthreads();
    #pragma unroll
    for (int i = 0; i < 4; i++) {
        int n = n0 + ty + i * 8;
        float v = t[tx][ty + i * 8];
        __nv_bfloat16 h = __float2bfloat16(v);
        __nv_bfloat16 l = __float2bfloat16(v - __bfloat162float(h));
        Th[(size_t)n * K + k0 + tx] = reinterpret_cast<uint16_t&>(h);
        Tl[(size_t)n * K + k0 + tx] = reinterpret_cast<uint16_t&>(l);
    }
}

// ---------------------------------------------------------------------------
// bf16x3 HMMA GEMM: BM=64, BN=64, BK=32, 128 threads (4 warps, 32x32 each),
// 3-stage cp.async, 1 sync/chunk. Grid >= 512 blocks -> 3 blocks/SM.
// B stored [N][K] (K-major) -> non-trans ldmatrix.
// Merged-QK routing: colBase >= 512 -> second output (K), else first (Q*scale1).
// ---------------------------------------------------------------------------
#define GSTR 40
#define G_APL (64*GSTR)          // one plane, elems
#define G_STG (4*G_APL)          // stage elems (Ah,Al,Bh,Bl)

__global__ __launch_bounds__(128) void gemm_tc(
    const uint16_t* __restrict__ A1h, const uint16_t* __restrict__ A1l,
    const uint16_t* __restrict__ A2h, const uint16_t* __restrict__ A2l,
    const uint16_t* __restrict__ Bth, const uint16_t* __restrict__ Btl,
    const float* __restrict__ bias1, const float* __restrict__ bias2,
    float* __restrict__ Cf,
    uint16_t* __restrict__ Ch,  uint16_t* __restrict__ Cl,
    uint16_t* __restrict__ Ch2, uint16_t* __restrict__ Cl2,
    int K, float scale1)
{
    extern __shared__ uint16_t sm[];
    const int tid  = threadIdx.x;
    const int lane = tid & 31, wid = tid >> 5;
    const int grp  = lane >> 2, tig = lane & 3;
    const int wm = (wid & 1) * 32, wn = (wid >> 1) * 32;
    const int rowBase = blockIdx.y * 64, colBase = blockIdx.x * 64;

    const int arow = ((lane >> 3) & 1) * 8 + (lane & 7);   // A ldsm pattern
    const int acol = (lane >> 4) * 8;
    const int brow = (lane >> 4) * 8 + (lane & 7);          // B non-trans pattern
    const int bcol = ((lane >> 3) & 1) * 8;

    float acc[2][4][4];
    #pragma unroll
    for (int mt = 0; mt < 2; mt++)
        #pragma unroll
        for (int nt = 0; nt < 4; nt++)
            #pragma unroll
            for (int j = 0; j < 4; j++) acc[mt][nt][j] = 0.f;

    const int NIT = K / 32;
    const uint32_t base = smem_u32(sm);

    auto load_chunk = [&](int it) {
        uint32_t sb = base + (it % 3) * G_STG * 2;
        int k0 = it * 32;
        const uint16_t* Ah_ = (k0 < Dd) ? A1h : A2h;
        const uint16_t* Al_ = (k0 < Dd) ? A1l : A2l;
        int ka = k0 & (Dd - 1);
        #pragma unroll
        for (int i = 0; i < 2; i++) {
            int idx = tid + i * 128;
            int r = idx >> 2, ch = idx & 3;
            size_t ga = (size_t)(rowBase + r) * Dd + ka + ch * 8;
            size_t gb = (size_t)(colBase + r) * K + k0 + ch * 8;
            uint32_t d = (r * GSTR + ch * 8) * 2;
            cpa16(sb + d,                Ah_ + ga);
            cpa16(sb + G_APL * 2 + d,    Al_ + ga);
            cpa16(sb + 2 * G_APL * 2 + d, Bth + gb);
            cpa16(sb + 3 * G_APL * 2 + d, Btl + gb);
        }
        cpa_commit();
    };

    load_chunk(0);
    load_chunk(1);

    for (int it = 0; it < NIT; it++) {
        if (it + 1 < NIT) cpa_wait<1>(); else cpa_wait<0>();
        __syncthreads();
        if (it + 2 < NIT) load_chunk(it + 2);

        const uint16_t* Ah = sm + (it % 3) * G_STG;
        const uint16_t* Al = Ah + G_APL;
        const uint16_t* Bh = Ah + 2 * G_APL;
        const uint16_t* Bl = Ah + 3 * G_APL;

        #pragma unroll
        for (int kk = 0; kk < 2; kk++) {
            uint32_t ah[2][4], al[2][4];
            #pragma unroll
            for (int mt = 0; mt < 2; mt++) {
                int off = (wm + mt * 16 + arow) * GSTR + kk * 16 + acol;
                ldsm_x4(ah[mt], smem_u32(&Ah[off]));
                ldsm_x4(al[mt], smem_u32(&Al[off]));
            }
            #pragma unroll
            for (int g = 0; g < 2; g++) {
                uint32_t bh4[4], bl4[4];
                int off = (wn + g * 16 + brow) * GSTR + kk * 16 + bcol;
                ldsm_x4(bh4, smem_u32(&Bh[off]));
                ldsm_x4(bl4, smem_u32(&Bl[off]));
                #pragma unroll
                for (int mt = 0; mt < 2; mt++) {
                    mma16816(acc[mt][2*g],   ah[mt], bh4);
                    mma16816(acc[mt][2*g],   al[mt], bh4);
                    mma16816(acc[mt][2*g],   ah[mt], bl4);
                    mma16816(acc[mt][2*g+1], ah[mt], bh4 + 2);
                    mma16816(acc[mt][2*g+1], al[mt], bh4 + 2);
                    mma16816(acc[mt][2*g+1], ah[mt], bl4 + 2);
                }
            }
        }
        __syncthreads();
    }

    const bool second = (colBase >= Dd);
    const float xscale = second ? 1.f : scale1;
    const float* bias = second ? bias2 : bias1;
    uint16_t* Dh = second ? Ch2 : Ch;
    uint16_t* Dl = second ? Cl2 : Cl;
    const int colOff = second ? (colBase - Dd) : colBase;

    #pragma unroll
    for (int mt = 0; mt < 2; mt++)
        #pragma unroll
        for (int nt = 0; nt < 4; nt++) {
            int row = rowBase + wm + mt * 16 + grp;
            int col = colOff + wn + nt * 8 + 2 * tig;
            float bx = bias[col], by = bias[col + 1];
            float v00 = (acc[mt][nt][0] + bx) * xscale;
            float v01 = (acc[mt][nt][1] + by) * xscale;
            float v10 = (acc[mt][nt][2] + bx) * xscale;
            float v11 = (acc[mt][nt][3] + by) * xscale;
            if (Cf) {
                *(float2*)(Cf + (size_t)row * Dd + col)       = make_float2(v00, v01);
                *(float2*)(Cf + (size_t)(row + 8) * Dd + col) = make_float2(v10, v11);
            } else {
                uint32_t h0, l0, h1, l1;
                split2(v00, v01, h0, l0);
                split2(v10, v11, h1, l1);
                *(uint32_t*)&Dh[(size_t)row * Dd + col]       = h0;
                *(uint32_t*)&Dl[(size_t)row * Dd + col]       = l0;
                *(uint32_t*)&Dh[(size_t)(row + 8) * Dd + col] = h1;
                *(uint32_t*)&Dl[(size_t)(row + 8) * Dd + col] = l1;
            }
        }
}

// ---------------------------------------------------------------------------
// Flash attention: BQ=64 (4 warps x m16), BK=32, 3-stage cp.async (55 KB ->
// 2 blocks/SM). Fixed-base softmax: scores are O(1) so exp() cannot overflow
// (clamped at 60 for paranoia); no online max, no rescale. Masked p = 0, so
// l == reference's sum|A|.
// ---------------------------------------------------------------------------
#define FSTR 72
#define F_PL  (32*FSTR)        // one K/V plane per stage, elems
#define F_STG (4*F_PL)         // stage elems (Kh,Kl,Vh,Vl) = 9216

__global__ __launch_bounds__(128) void flash_bf3_kernel(
    const uint16_t* __restrict__ Qh, const uint16_t* __restrict__ Ql,
    const uint16_t* __restrict__ Kgh, const uint16_t* __restrict__ Kgl,
    const uint16_t* __restrict__ Vgh, const uint16_t* __restrict__ Vgl,
    const uint32_t* __restrict__ mbits,
    uint16_t* __restrict__ Oh, uint16_t* __restrict__ Ol)
{
    extern __shared__ uint16_t sm[];
    const int tid = threadIdx.x, lane = tid & 31, w = tid >> 5;
    const int grp = lane >> 2, tig = lane & 3;
    const int b = blockIdx.y >> 3, h = blockIdx.y & 7;
    const int q0 = blockIdx.x * 64;

    const int arow = ((lane >> 3) & 1) * 8 + (lane & 7);
    const int acol = (lane >> 4) * 8;
    const int brow = (lane >> 4) * 8 + (lane & 7);
    const int bcol = ((lane >> 3) & 1) * 8;

    // ---- stage Q (64 x 64, hi/lo) through stage buffers, pull A-frags ----
    {
        uint32_t base = smem_u32(sm);
        #pragma unroll
        for (int i = 0; i < 4; i++) {
            int chunk = tid + i * 128;
            int r = chunk >> 3, c = (chunk & 7) * 8;
            const size_t g = (size_t)(b * Ss + q0 + r) * Dd + h * HDIM + c;
            cpa16(base + (r * FSTR + c) * 2,                 Qh + g);
            cpa16(base + (64 * FSTR + r * FSTR + c) * 2,     Ql + g);
        }
        cpa_commit();
        cpa_wait<0>();
        __syncthreads();
    }
    uint32_t qh[4][4], ql[4][4];
    #pragma unroll
    for (int c = 0; c < 4; c++) {
        int off = (w * 16 + arow) * FSTR + c * 16 + acol;
        ldsm_x4(qh[c], smem_u32(&sm[off]));
        ldsm_x4(ql[c], smem_u32(&sm[64 * FSTR + off]));
    }
    __syncthreads();

    float oacc[8][4];
    #pragma unroll
    for (int n = 0; n < 8; n++)
        #pragma unroll
        for (int j = 0; j < 4; j++) oacc[n][j] = 0.f;
    float lrun[2] = {0.f, 0.f};

    auto load_tile = [&](int it) {
        int k0 = it * 32;
        uint32_t base = smem_u32(sm) + (it % 3) * F_STG * 2;
        #pragma unroll
        for (int i = 0; i < 2; i++) {
            int chunk = tid + i * 128;
            int r = chunk >> 3, c = (chunk & 7) * 8;   // r 0..31
            const size_t g = (size_t)(b * Ss + k0 + r) * Dd + h * HDIM + c;
            uint32_t d = (r * FSTR + c) * 2;
            cpa16(base + d,                Kgh + g);
            cpa16(base + F_PL * 2 + d,     Kgl + g);
            cpa16(base + 2 * F_PL * 2 + d, Vgh + g);
            cpa16(base + 3 * F_PL * 2 + d, Vgl + g);
        }
        cpa_commit();
    };

    load_tile(0);
    load_tile(1);

    const int NT = Ss / 32;
    for (int it = 0; it < NT; it++) {
        if (it + 1 < NT) cpa_wait<1>(); else cpa_wait<0>();
        __syncthreads();
        if (it + 2 < NT) load_tile(it + 2);

        const uint16_t* Kh = sm + (it % 3) * F_STG;
        const uint16_t* Kl = Kh + F_PL;
        const uint16_t* Vh = Kh + 2 * F_PL;
        const uint16_t* Vl = Kh + 3 * F_PL;
        const int k0 = it * 32;

        // S = Qs @ K^T  (m16 x n32)
        float sacc[4][4];
        #pragma unroll
        for (int n = 0; n < 4; n++)
            #pragma unroll
            for (int j = 0; j < 4; j++) sacc[n][j] = 0.f;
        #pragma unroll
        for (int g = 0; g < 2; g++)
            #pragma unroll
            for (int c = 0; c < 4; c++) {
                uint32_t kf[4], kfl[4];
                int off = (g * 16 + brow) * FSTR + c * 16 + bcol;
                ldsm_x4(kf,  smem_u32(&Kh[off]));
                ldsm_x4(kfl, smem_u32(&Kl[off]));
                mma16816(sacc[2*g],   qh[c], kf);
                mma16816(sacc[2*g],   ql[c], kf);
                mma16816(sacc[2*g],   qh[c], kfl);
                mma16816(sacc[2*g+1], qh[c], kf + 2);
                mma16816(sacc[2*g+1], ql[c], kf + 2);
                mma16816(sacc[2*g+1], qh[c], kfl + 2);
            }

        // ---- masked softmax (fixed base; no max tracking) ----
        #pragma unroll
        for (int r = 0; r < 2; r++) {
            int qrow = q0 + w * 16 + grp + r * 8;
            uint32_t bw = mbits[((size_t)(b * Ss) + qrow) * (Ss / 32) + (k0 >> 5)];
            float ps = 0.f;
            #pragma unroll
            for (int n = 0; n < 4; n++)
                #pragma unroll
                for (int e = 0; e < 2; e++) {
                    int col = n * 8 + 2 * tig + e;
                    uint32_t on = (bw >> col) & 1u;
                    float p = on ? __expf(fminf(sacc[n][r*2+e], 60.f)) : 0.f;
                    sacc[n][r*2+e] = p;
                    ps += p;
                }
            ps += __shfl_xor_sync(0xffffffffu, ps, 1);
            ps += __shfl_xor_sync(0xffffffffu, ps, 2);
            lrun[r] += ps;
        }

        // ---- O += P @ V  (P c-frags -> A-frags) ----
        #pragma unroll
        for (int kc = 0; kc < 2; kc++) {
            uint32_t ah[4], al[4];
            split2(sacc[2*kc][0],   sacc[2*kc][1],   ah[0], al[0]);
            split2(sacc[2*kc][2],   sacc[2*kc][3],   ah[1], al[1]);
            split2(sacc[2*kc+1][0], sacc[2*kc+1][1], ah[2], al[2]);
            split2(sacc[2*kc+1][2], sacc[2*kc+1][3], ah[3], al[3]);
            #pragma unroll
            for (int c = 0; c < 4; c++) {
                uint32_t vf[4], vfl[4];
                int off = (kc * 16 + arow) * FSTR + c * 16 + acol;
                ldsm_x4_t(vf,  smem_u32(&Vh[off]));
                ldsm_x4_t(vfl, smem_u32(&Vl[off]));
                mma16816(oacc[2*c],   ah, vf);
                mma16816(oacc[2*c],   al, vf);
                mma16816(oacc[2*c],   ah, vfl);
                mma16816(oacc[2*c+1], ah, vf + 2);
                mma16816(oacc[2*c+1], al, vf + 2);
                mma16816(oacc[2*c+1], ah, vfl + 2);
            }
        }
    }

    // ---- epilogue: divide by l (== sum|A|), write hi/lo planes ----
    float inv0 = (lrun[0] > 0.f) ? 1.f / lrun[0] : 0.f;
    float inv1 = (lrun[1] > 0.f) ? 1.f / lrun[1] : 0.f;
    int row0 = b * Ss + q0 + w * 16 + grp;
    #pragma unroll
    for (int n = 0; n < 8; n++) {
        int col = h * HDIM + n * 8 + 2 * tig;
        uint32_t h0, l0, h1, l1;
        split2(oacc[n][0] * inv0, oacc[n][1] * inv0, h0, l0);
        split2(oacc[n][2] * inv1, oacc[n][3] * inv1, h1, l1);
        *(uint32_t*)&Oh[(size_t)row0 * Dd + col]       = h0;
        *(uint32_t*)&Ol[(size_t)row0 * Dd + col]       = l0;
        *(uint32_t*)&Oh[(size_t)(row0 + 8) * Dd + col] = h1;
        *(uint32_t*)&Ol[(size_t)(row0 + 8) * Dd + col] = l1;
    }
}

// ---------------------------------------------------------------------------
extern "C" void kernel_launch(void* const* d_in, const int* in_sizes, int n_in,
                              void* d_out, int out_size)
{
    const float* gene = (const float*)d_in[0];
    const float* expr = (const float*)d_in[1];
    const float* Mm   = (const float*)d_in[2];
    const float* Wf   = (const float*)d_in[3];
    const float* bf   = (const float*)d_in[4];
    const float* Wq   = (const float*)d_in[5];
    const float* bq   = (const float*)d_in[6];
    const float* Wk   = (const float*)d_in[7];
    const float* bk   = (const float*)d_in[8];
    const float* Wv   = (const float*)d_in[9];
    const float* bv   = (const float*)d_in[10];
    const float* Wo   = (const float*)d_in[11];
    const float* bo   = (const float*)d_in[12];
    float* out = (float*)d_out;

    uint16_t *geneh, *genel, *exprh, *exprl, *fush, *fusl;
    uint16_t *qh, *ql, *kh, *kl, *vh, *vl, *ath, *atl;
    uint16_t *wtfh, *wtfl, *wtqkh, *wtqkl, *wtvh, *wtvl, *wtoh, *wtol;
    uint32_t* mbits;
    cudaGetSymbolAddress((void**)&geneh, g_gene_h); cudaGetSymbolAddress((void**)&genel, g_gene_l);
    cudaGetSymbolAddress((void**)&exprh, g_expr_h); cudaGetSymbolAddress((void**)&exprl, g_expr_l);
    cudaGetSymbolAddress((void**)&fush,  g_fus_h);  cudaGetSymbolAddress((void**)&fusl,  g_fus_l);
    cudaGetSymbolAddress((void**)&qh,    g_q_h);    cudaGetSymbolAddress((void**)&ql,    g_q_l);
    cudaGetSymbolAddress((void**)&kh,    g_k_h);    cudaGetSymbolAddress((void**)&kl,    g_k_l);
    cudaGetSymbolAddress((void**)&vh,    g_v_h);    cudaGetSymbolAddress((void**)&vl,    g_v_l);
    cudaGetSymbolAddress((void**)&ath,   g_at_h);   cudaGetSymbolAddress((void**)&atl,   g_at_l);
    cudaGetSymbolAddress((void**)&wtfh,  g_wtf_h);  cudaGetSymbolAddress((void**)&wtfl,  g_wtf_l);
    cudaGetSymbolAddress((void**)&wtqkh, g_wtqk_h); cudaGetSymbolAddress((void**)&wtqkl, g_wtqk_l);
    cudaGetSymbolAddress((void**)&wtvh,  g_wtv_h);  cudaGetSymbolAddress((void**)&wtvl,  g_wtv_l);
    cudaGetSymbolAddress((void**)&wtoh,  g_wto_h);  cudaGetSymbolAddress((void**)&wtol,  g_wto_l);
    cudaGetSymbolAddress((void**)&mbits, g_mbits);

    const int SMG = 3 * G_STG * 2;     // 61440 B
    const int SMF = 3 * F_STG * 2;     // 55296 B
    cudaFuncSetAttribute(gemm_tc, cudaFuncAttributeMaxDynamicSharedMemorySize, SMG);
    cudaFuncSetAttribute(flash_bf3_kernel, cudaFuncAttributeMaxDynamicSharedMemorySize, SMF);
    cudaFuncSetAttribute(gemm_tc, cudaFuncAttributePreferredSharedMemoryCarveout, 90);
    cudaFuncSetAttribute(flash_bf3_kernel, cudaFuncAttributePreferredSharedMemoryCarveout, 60);

    const int NE = Bb * Ss * Dd;
    maskbits_kernel<<<(Bb * Ss * Ss) / 256, 256>>>(Mm, mbits);
    split_kernel<<<NE / 1024, 256>>>(gene, geneh, genel);
    split_kernel<<<NE / 1024, 256>>>(expr, exprh, exprl);
    transpose_split_kernel<<<dim3(Dd / 32, (2 * Dd) / 32), 256>>>(Wf, wtfh, wtfl, 2 * Dd, Dd);
    transpose_split_kernel<<<dim3(Dd / 32, Dd / 32), 256>>>(Wq, wtqkh, wtqkl, Dd, Dd);
    transpose_split_kernel<<<dim3(Dd / 32, Dd / 32), 256>>>(Wk, wtqkh + (size_t)Dd * Dd,
                                                            wtqkl + (size_t)Dd * Dd, Dd, Dd);
    transpose_split_kernel<<<dim3(Dd / 32, Dd / 32), 256>>>(Wv, wtvh, wtvl, Dd, Dd);
    transpose_split_kernel<<<dim3(Dd / 32, Dd / 32), 256>>>(Wo, wtoh, wtol, Dd, Dd);

    const int MR = Bb * Ss;                       // 4096
    // fused = [gene; expr] @ Wf + bf  (K=1024)
    gemm_tc<<<dim3(Dd / 64, MR / 64), 128, SMG>>>(
        geneh, genel, exprh, exprl, wtfh, wtfl, bf, bf,
        nullptr, fush, fusl, nullptr, nullptr, 2 * Dd, 1.f);
    // merged QK: N=1024; first half -> Q (x SCALE), second half -> K
    gemm_tc<<<dim3((2 * Dd) / 64, MR / 64), 128, SMG>>>(
        fush, fusl, fush, fusl, wtqkh, wtqkl, bq, bk,
        nullptr, qh, ql, kh, kl, Dd, SCALE);
    gemm_tc<<<dim3(Dd / 64, MR / 64), 128, SMG>>>(
        exprh, exprl, exprh, exprl, wtvh, wtvl, bv, bv,
        nullptr, vh, vl, nullptr, nullptr, Dd, 1.f);

    flash_bf3_kernel<<<dim3(Ss / 64, Bb * Hh), 128, SMF>>>(
        qh, ql, kh, kl, vh, vl, mbits, ath, atl);

    gemm_tc<<<dim3(Dd / 64, MR / 64), 128, SMG>>>(
        ath, atl, ath, atl, wtoh, wtol, bo, bo,
        out, nullptr, nullptr, nullptr, nullptr, Dd, 1.f);
}

// round 9
// speedup vs baseline: 1.1499x; 1.1326x over previous
#include <cuda_runtime.h>
#include <cuda_bf16.h>
#include <cstdint>

#define Bb 2
#define Ss 2048
#define Dd 512
#define Hh 8
#define HDIM 64
#define SCALE 0.125f

// ---------------------------------------------------------------------------
// Device-global scratch
// ---------------------------------------------------------------------------
__device__ uint16_t g_gene_h[Bb*Ss*Dd], g_gene_l[Bb*Ss*Dd];
__device__ uint16_t g_expr_h[Bb*Ss*Dd], g_expr_l[Bb*Ss*Dd];
__device__ uint16_t g_fus_h[Bb*Ss*Dd],  g_fus_l[Bb*Ss*Dd];
__device__ uint16_t g_q_h[Bb*Ss*Dd],    g_q_l[Bb*Ss*Dd];
__device__ uint16_t g_k_h[Bb*Ss*Dd],    g_k_l[Bb*Ss*Dd];
__device__ uint16_t g_v_h[Bb*Ss*Dd],    g_v_l[Bb*Ss*Dd];
__device__ uint16_t g_at_h[Bb*Ss*Dd],   g_at_l[Bb*Ss*Dd];
__device__ uint16_t g_wtf_h[Dd*2*Dd],   g_wtf_l[Dd*2*Dd];       // [512][1024]
__device__ uint16_t g_wtqkv_h[3*Dd*Dd], g_wtqkv_l[3*Dd*Dd];     // [1536][512]
__device__ uint16_t g_wto_h[Dd*Dd],     g_wto_l[Dd*Dd];
__device__ uint32_t g_mbits[Bb*Ss*(Ss/32)];

// ---------------------------------------------------------------------------
// Helpers
// ---------------------------------------------------------------------------
__device__ __forceinline__ uint32_t smem_u32(const void* p) {
    return (uint32_t)__cvta_generic_to_shared(p);
}
__device__ __forceinline__ void split2(float x, float y, uint32_t &hi, uint32_t &lo) {
    __nv_bfloat162 h = __floats2bfloat162_rn(x, y);
    float2 hf = __bfloat1622float2(h);
    __nv_bfloat162 l = __floats2bfloat162_rn(x - hf.x, y - hf.y);
    hi = reinterpret_cast<uint32_t&>(h);
    lo = reinterpret_cast<uint32_t&>(l);
}
__device__ __forceinline__ void mma16816(float c[4], const uint32_t* a, const uint32_t* b) {
    asm volatile(
        "mma.sync.aligned.m16n8k16.row.col.f32.bf16.bf16.f32 "
        "{%0,%1,%2,%3}, {%4,%5,%6,%7}, {%8,%9}, {%0,%1,%2,%3};\n"
        : "+f"(c[0]), "+f"(c[1]), "+f"(c[2]), "+f"(c[3])
        : "r"(a[0]), "r"(a[1]), "r"(a[2]), "r"(a[3]), "r"(b[0]), "r"(b[1]));
}
__device__ __forceinline__ void ldsm_x4(uint32_t a[4], uint32_t addr) {
    asm volatile("ldmatrix.sync.aligned.m8n8.x4.shared.b16 {%0,%1,%2,%3}, [%4];"
        : "=r"(a[0]), "=r"(a[1]), "=r"(a[2]), "=r"(a[3]) : "r"(addr));
}
__device__ __forceinline__ void ldsm_x4_t(uint32_t a[4], uint32_t addr) {
    asm volatile("ldmatrix.sync.aligned.m8n8.x4.trans.shared.b16 {%0,%1,%2,%3}, [%4];"
        : "=r"(a[0]), "=r"(a[1]), "=r"(a[2]), "=r"(a[3]) : "r"(addr));
}
__device__ __forceinline__ void cpa16(uint32_t dst, const void* src) {
    asm volatile("cp.async.cg.shared.global [%0], [%1], 16;" :: "r"(dst), "l"(src));
}
__device__ __forceinline__ void cpa_commit() { asm volatile("cp.async.commit_group;"); }
template<int N> __device__ __forceinline__ void cpa_wait() {
    asm volatile("cp.async.wait_group %0;" :: "n"(N) : "memory");
}

// ---------------------------------------------------------------------------
// Pre-pass kernels (launch-count compressed)
// ---------------------------------------------------------------------------
__global__ __launch_bounds__(256) void maskbits_kernel(const float* __restrict__ M,
                                                       uint32_t* __restrict__ bits) {
    int idx = blockIdx.x * 256 + threadIdx.x;
    float v = M[idx];
    uint32_t b = __ballot_sync(0xffffffffu, v != 0.f);
    if ((threadIdx.x & 31) == 0) bits[idx >> 5] = b;
}

// grid.y = 2: y0 gene, y1 expr
__global__ __launch_bounds__(256) void split_kernel(
    const float* __restrict__ in0, uint16_t* __restrict__ hi0, uint16_t* __restrict__ lo0,
    const float* __restrict__ in1, uint16_t* __restrict__ hi1, uint16_t* __restrict__ lo1)
{
    const float* in = blockIdx.y ? in1 : in0;
    uint16_t* hi = blockIdx.y ? hi1 : hi0;
    uint16_t* lo = blockIdx.y ? lo1 : lo0;
    int i = (blockIdx.x * 256 + threadIdx.x) * 4;
    float4 v = *(const float4*)(in + i);
    uint32_t h0, l0, h1, l1;
    split2(v.x, v.y, h0, l0);
    split2(v.z, v.w, h1, l1);
    *(uint2*)(hi + i) = make_uint2(h0, h1);
    *(uint2*)(lo + i) = make_uint2(l0, l1);
}

// All 5 weight transposes in one launch. grid = (16, 96).
__global__ __launch_bounds__(256) void transpose_all_kernel(
    const float* __restrict__ Wf, const float* __restrict__ Wq,
    const float* __restrict__ Wk, const float* __restrict__ Wv,
    const float* __restrict__ Wo,
    uint16_t* __restrict__ Tfh, uint16_t* __restrict__ Tfl,
    uint16_t* __restrict__ Tqkvh, uint16_t* __restrict__ Tqkvl,
    uint16_t* __restrict__ Toh, uint16_t* __restrict__ Tol)
{
    __shared__ float t[32][33];
    const float* W; uint16_t *Th, *Tl; int K, kt;
    int y = blockIdx.y;
    if (y < 32)      { W = Wf; Th = Tfh; Tl = Tfl; K = 1024; kt = y; }
    else if (y < 48) { W = Wq; Th = Tqkvh; Tl = Tqkvl; K = 512; kt = y - 32; }
    else if (y < 64) { W = Wk; Th = Tqkvh + (size_t)Dd * Dd; Tl = Tqkvl + (size_t)Dd * Dd; K = 512; kt = y - 48; }
    else if (y < 80) { W = Wv; Th = Tqkvh + (size_t)2 * Dd * Dd; Tl = Tqkvl + (size_t)2 * Dd * Dd; K = 512; kt = y - 64; }
    else             { W = Wo; Th = Toh; Tl = Tol; K = 512; kt = y - 80; }

    int n0 = blockIdx.x * 32, k0 = kt * 32;
    int tx = threadIdx.x & 31, ty = threadIdx.x >> 5;
    #pragma unroll
    for (int i = 0; i < 4; i++) {
        int k = k0 + ty + i * 8;
        t[ty + i * 8][tx] = W[(size_t)k * Dd + n0 + tx];
    }
    __syncthreads();
    #pragma unroll
    for (int i = 0; i < 4; i++) {
        int n = n0 + ty + i * 8;
        float v = t[tx][ty + i * 8];
        __nv_bfloat16 h = __float2bfloat16(v);
        __nv_bfloat16 l = __float2bfloat16(v - __bfloat162float(h));
        Th[(size_t)n * K + k0 + tx] = reinterpret_cast<uint16_t&>(h);
        Tl[(size_t)n * K + k0 + tx] = reinterpret_cast<uint16_t&>(l);
    }
}

// ---------------------------------------------------------------------------
// bf16x3 HMMA GEMM, 64x64 warp tiles: BM=128, BN=128, BK=32, 128 threads
// (4 warps, 2m x 2n), 2-stage cp.async. B stored [N][K] (K-major).
// N-segment routing (for merged QKV): seg = gcol>>9; seg2 uses A3 planes.
// ---------------------------------------------------------------------------
#define GSTR 40
#define G_PL  (128*GSTR)         // one plane per stage, elems (5120)
#define G_STG (4*G_PL)           // stage elems (Ah,Al,Bh,Bl) = 20480

__global__ __launch_bounds__(128) void gemm_tc(
    const uint16_t* __restrict__ A1h, const uint16_t* __restrict__ A1l,
    const uint16_t* __restrict__ A2h, const uint16_t* __restrict__ A2l,
    const uint16_t* __restrict__ A3h, const uint16_t* __restrict__ A3l,
    const uint16_t* __restrict__ Bth, const uint16_t* __restrict__ Btl,
    const float* __restrict__ bias0, const float* __restrict__ bias1,
    const float* __restrict__ bias2,
    float* __restrict__ Cf,
    uint16_t* __restrict__ O0h, uint16_t* __restrict__ O0l,
    uint16_t* __restrict__ O1h, uint16_t* __restrict__ O1l,
    uint16_t* __restrict__ O2h, uint16_t* __restrict__ O2l,
    int K, float scale0)
{
    extern __shared__ uint16_t sm[];
    const int tid  = threadIdx.x;
    const int lane = tid & 31, wid = tid >> 5;
    const int grp  = lane >> 2, tig = lane & 3;
    const int wm = (wid & 1) * 64, wn = (wid >> 1) * 64;
    const int rowBase = blockIdx.y * 128, colBase = blockIdx.x * 128;
    const int seg = colBase >> 9;      // 512-column segment (block never straddles)

    const int arow = ((lane >> 3) & 1) * 8 + (lane & 7);
    const int acol = (lane >> 4) * 8;
    const int brow = (lane >> 4) * 8 + (lane & 7);
    const int bcol = ((lane >> 3) & 1) * 8;

    float acc[4][8][4];
    #pragma unroll
    for (int mt = 0; mt < 4; mt++)
        #pragma unroll
        for (int nt = 0; nt < 8; nt++)
            #pragma unroll
            for (int j = 0; j < 4; j++) acc[mt][nt][j] = 0.f;

    const int NIT = K / 32;
    const uint32_t base = smem_u32(sm);

    auto load_chunk = [&](int it) {
        uint32_t sb = base + (it & 1) * G_STG * 2;
        int k0 = it * 32;
        const uint16_t* Ah_ = (seg == 2) ? A3h : ((k0 < Dd) ? A1h : A2h);
        const uint16_t* Al_ = (seg == 2) ? A3l : ((k0 < Dd) ? A1l : A2l);
        int ka = k0 & (Dd - 1);
        #pragma unroll
        for (int i = 0; i < 4; i++) {
            int idx = tid + i * 128;
            int r = idx >> 2, ch = idx & 3;
            size_t ga = (size_t)(rowBase + r) * Dd + ka + ch * 8;
            size_t gb = (size_t)(colBase + r) * K + k0 + ch * 8;
            uint32_t d = (r * GSTR + ch * 8) * 2;
            cpa16(sb + d,                 Ah_ + ga);
            cpa16(sb + G_PL * 2 + d,      Al_ + ga);
            cpa16(sb + 2 * G_PL * 2 + d,  Bth + gb);
            cpa16(sb + 3 * G_PL * 2 + d,  Btl + gb);
        }
        cpa_commit();
    };

    load_chunk(0);

    for (int it = 0; it < NIT; it++) {
        cpa_wait<0>();
        __syncthreads();
        if (it + 1 < NIT) load_chunk(it + 1);

        const uint16_t* Ah = sm + (it & 1) * G_STG;
        const uint16_t* Al = Ah + G_PL;
        const uint16_t* Bh = Ah + 2 * G_PL;
        const uint16_t* Bl = Ah + 3 * G_PL;

        #pragma unroll
        for (int kk = 0; kk < 2; kk++) {
            uint32_t ah[4][4], al[4][4];
            #pragma unroll
            for (int mt = 0; mt < 4; mt++) {
                int off = (wm + mt * 16 + arow) * GSTR + kk * 16 + acol;
                ldsm_x4(ah[mt], smem_u32(&Ah[off]));
                ldsm_x4(al[mt], smem_u32(&Al[off]));
            }
            #pragma unroll
            for (int g = 0; g < 4; g++) {
                uint32_t bh4[4], bl4[4];
                int off = (wn + g * 16 + brow) * GSTR + kk * 16 + bcol;
                ldsm_x4(bh4, smem_u32(&Bh[off]));
                ldsm_x4(bl4, smem_u32(&Bl[off]));
                #pragma unroll
                for (int mt = 0; mt < 4; mt++) {
                    mma16816(acc[mt][2*g],   ah[mt], bh4);
                    mma16816(acc[mt][2*g],   al[mt], bh4);
                    mma16816(acc[mt][2*g],   ah[mt], bl4);
                    mma16816(acc[mt][2*g+1], ah[mt], bh4 + 2);
                    mma16816(acc[mt][2*g+1], al[mt], bh4 + 2);
                    mma16816(acc[mt][2*g+1], ah[mt], bl4 + 2);
                }
            }
        }
        __syncthreads();
    }

    const float xscale = (seg == 0) ? scale0 : 1.f;
    const float* bias = (seg == 0) ? bias0 : ((seg == 1) ? bias1 : bias2);
    uint16_t* Dh = (seg == 0) ? O0h : ((seg == 1) ? O1h : O2h);
    uint16_t* Dl = (seg == 0) ? O0l : ((seg == 1) ? O1l : O2l);
    const int colOff = colBase - seg * 512;

    #pragma unroll
    for (int mt = 0; mt < 4; mt++)
        #pragma unroll
        for (int nt = 0; nt < 8; nt++) {
            int row = rowBase + wm + mt * 16 + grp;
            int col = colOff + wn + nt * 8 + 2 * tig;
            float bx = bias[col], by = bias[col + 1];
            float v00 = (acc[mt][nt][0] + bx) * xscale;
            float v01 = (acc[mt][nt][1] + by) * xscale;
            float v10 = (acc[mt][nt][2] + bx) * xscale;
            float v11 = (acc[mt][nt][3] + by) * xscale;
            if (Cf) {
                *(float2*)(Cf + (size_t)row * Dd + col)       = make_float2(v00, v01);
                *(float2*)(Cf + (size_t)(row + 8) * Dd + col) = make_float2(v10, v11);
            } else {
                uint32_t h0, l0, h1, l1;
                split2(v00, v01, h0, l0);
                split2(v10, v11, h1, l1);
                *(uint32_t*)&Dh[(size_t)row * Dd + col]       = h0;
                *(uint32_t*)&Dl[(size_t)row * Dd + col]       = l0;
                *(uint32_t*)&Dh[(size_t)(row + 8) * Dd + col] = h1;
                *(uint32_t*)&Dl[(size_t)(row + 8) * Dd + col] = l1;
            }
        }
}

// ---------------------------------------------------------------------------
// Flash attention: BQ=128 (4 warps, m32 each), BK=32, 3-stage cp.async.
// Q_hi frags in registers; Q_lo re-read per-tile from a persistent smem plane.
// Fixed-base softmax (scores O(1), clamp 60). Masked p = 0 => l == sum|A|.
// ---------------------------------------------------------------------------
#define FSTR 72
#define F_PL  (32*FSTR)        // 2304
#define F_STG (4*F_PL)         // 9216
#define QLO_OFF (3*F_STG)      // Q_lo plane: 128*FSTR = 9216 elems

__global__ __launch_bounds__(128) void flash_bf3_kernel(
    const uint16_t* __restrict__ Qh, const uint16_t* __restrict__ Ql,
    const uint16_t* __restrict__ Kgh, const uint16_t* __restrict__ Kgl,
    const uint16_t* __restrict__ Vgh, const uint16_t* __restrict__ Vgl,
    const uint32_t* __restrict__ mbits,
    uint16_t* __restrict__ Oh, uint16_t* __restrict__ Ol)
{
    extern __shared__ uint16_t sm[];
    const int tid = threadIdx.x, lane = tid & 31, w = tid >> 5;
    const int grp = lane >> 2, tig = lane & 3;
    const int b = blockIdx.y >> 3, h = blockIdx.y & 7;
    const int q0 = blockIdx.x * 128;

    const int arow = ((lane >> 3) & 1) * 8 + (lane & 7);
    const int acol = (lane >> 4) * 8;
    const int brow = (lane >> 4) * 8 + (lane & 7);
    const int bcol = ((lane >> 3) & 1) * 8;

    // ---- load Q_hi into stage area (transient) + Q_lo into persistent plane ----
    {
        uint32_t base = smem_u32(sm);
        #pragma unroll
        for (int i = 0; i < 8; i++) {
            int chunk = tid + i * 128;
            int r = chunk >> 3, c = (chunk & 7) * 8;
            const size_t g = (size_t)(b * Ss + q0 + r) * Dd + h * HDIM + c;
            cpa16(base + (r * FSTR + c) * 2,             Qh + g);
            cpa16(base + (QLO_OFF + r * FSTR + c) * 2,   Ql + g);
        }
        cpa_commit();
        cpa_wait<0>();
        __syncthreads();
    }
    uint32_t qh[2][4][4];
    #pragma unroll
    for (int mt = 0; mt < 2; mt++)
        #pragma unroll
        for (int c = 0; c < 4; c++) {
            int off = (w * 32 + mt * 16 + arow) * FSTR + c * 16 + acol;
            ldsm_x4(qh[mt][c], smem_u32(&sm[off]));
        }
    __syncthreads();   // done with stage-area Q_hi

    float oacc[2][8][4];
    #pragma unroll
    for (int mt = 0; mt < 2; mt++)
        #pragma unroll
        for (int n = 0; n < 8; n++)
            #pragma unroll
            for (int j = 0; j < 4; j++) oacc[mt][n][j] = 0.f;
    float lrun[2][2] = {{0.f, 0.f}, {0.f, 0.f}};

    auto load_tile = [&](int it) {
        int k0 = it * 32;
        uint32_t base = smem_u32(sm) + (it % 3) * F_STG * 2;
        #pragma unroll
        for (int i = 0; i < 2; i++) {
            int chunk = tid + i * 128;
            int r = chunk >> 3, c = (chunk & 7) * 8;
            const size_t g = (size_t)(b * Ss + k0 + r) * Dd + h * HDIM + c;
            uint32_t d = (r * FSTR + c) * 2;
            cpa16(base + d,                Kgh + g);
            cpa16(base + F_PL * 2 + d,     Kgl + g);
            cpa16(base + 2 * F_PL * 2 + d, Vgh + g);
            cpa16(base + 3 * F_PL * 2 + d, Vgl + g);
        }
        cpa_commit();
    };

    load_tile(0);
    load_tile(1);

    const int NT = Ss / 32;
    for (int it = 0; it < NT; it++) {
        if (it + 1 < NT) cpa_wait<1>(); else cpa_wait<0>();
        __syncthreads();
        if (it + 2 < NT) load_tile(it + 2);

        const uint16_t* Kh = sm + (it % 3) * F_STG;
        const uint16_t* Kl = Kh + F_PL;
        const uint16_t* Vh = Kh + 2 * F_PL;
        const uint16_t* Vl = Kh + 3 * F_PL;
        const int k0 = it * 32;

        // ---- S = Qs @ K^T ----
        float sacc[2][4][4];
        #pragma unroll
        for (int mt = 0; mt < 2; mt++)
            #pragma unroll
            for (int n = 0; n < 4; n++)
                #pragma unroll
                for (int j = 0; j < 4; j++) sacc[mt][n][j] = 0.f;
        #pragma unroll
        for (int c = 0; c < 4; c++) {
            uint32_t qlo[2][4];
            #pragma unroll
            for (int mt = 0; mt < 2; mt++) {
                int qoff = QLO_OFF + (w * 32 + mt * 16 + arow) * FSTR + c * 16 + acol;
                ldsm_x4(qlo[mt], smem_u32(&sm[qoff]));
            }
            #pragma unroll
            for (int g = 0; g < 2; g++) {
                uint32_t kf[4], kfl[4];
                int off = (g * 16 + brow) * FSTR + c * 16 + bcol;
                ldsm_x4(kf,  smem_u32(&Kh[off]));
                ldsm_x4(kfl, smem_u32(&Kl[off]));
                #pragma unroll
                for (int mt = 0; mt < 2; mt++) {
                    mma16816(sacc[mt][2*g],   qh[mt][c], kf);
                    mma16816(sacc[mt][2*g],   qlo[mt],   kf);
                    mma16816(sacc[mt][2*g],   qh[mt][c], kfl);
                    mma16816(sacc[mt][2*g+1], qh[mt][c], kf + 2);
                    mma16816(sacc[mt][2*g+1], qlo[mt],   kf + 2);
                    mma16816(sacc[mt][2*g+1], qh[mt][c], kfl + 2);
                }
            }
        }

        // ---- masked softmax (fixed base) ----
        #pragma unroll
        for (int mt = 0; mt < 2; mt++)
            #pragma unroll
            for (int r = 0; r < 2; r++) {
                int qrow = q0 + w * 32 + mt * 16 + grp + r * 8;
                uint32_t bw = mbits[((size_t)(b * Ss) + qrow) * (Ss / 32) + (k0 >> 5)];
                float ps = 0.f;
                #pragma unroll
                for (int n = 0; n < 4; n++)
                    #pragma unroll
                    for (int e = 0; e < 2; e++) {
                        int col = n * 8 + 2 * tig + e;
                        uint32_t on = (bw >> col) & 1u;
                        float p = on ? __expf(fminf(sacc[mt][n][r*2+e], 60.f)) : 0.f;
                        sacc[mt][n][r*2+e] = p;
                        ps += p;
                    }
                ps += __shfl_xor_sync(0xffffffffu, ps, 1);
                ps += __shfl_xor_sync(0xffffffffu, ps, 2);
                lrun[mt][r] += ps;
            }

        // ---- O += P @ V ----
        #pragma unroll
        for (int kc = 0; kc < 2; kc++) {
            uint32_t ahh[2][4], all[2][4];
            #pragma unroll
            for (int mt = 0; mt < 2; mt++) {
                split2(sacc[mt][2*kc][0],   sacc[mt][2*kc][1],   ahh[mt][0], all[mt][0]);
                split2(sacc[mt][2*kc][2],   sacc[mt][2*kc][3],   ahh[mt][1], all[mt][1]);
                split2(sacc[mt][2*kc+1][0], sacc[mt][2*kc+1][1], ahh[mt][2], all[mt][2]);
                split2(sacc[mt][2*kc+1][2], sacc[mt][2*kc+1][3], ahh[mt][3], all[mt][3]);
            }
            #pragma unroll
            for (int c = 0; c < 4; c++) {
                uint32_t vf[4], vfl[4];
                int off = (kc * 16 + arow) * FSTR + c * 16 + acol;
                ldsm_x4_t(vf,  smem_u32(&Vh[off]));
                ldsm_x4_t(vfl, smem_u32(&Vl[off]));
                #pragma unroll
                for (int mt = 0; mt < 2; mt++) {
                    mma16816(oacc[mt][2*c],   ahh[mt], vf);
                    mma16816(oacc[mt][2*c],   all[mt], vf);
                    mma16816(oacc[mt][2*c],   ahh[mt], vfl);
                    mma16816(oacc[mt][2*c+1], ahh[mt], vf + 2);
                    mma16816(oacc[mt][2*c+1], all[mt], vf + 2);
                    mma16816(oacc[mt][2*c+1], ahh[mt], vfl + 2);
                }
            }
        }
    }

    // ---- epilogue ----
    #pragma unroll
    for (int mt = 0; mt < 2; mt++) {
        float inv0 = (lrun[mt][0] > 0.f) ? 1.f / lrun[mt][0] : 0.f;
        float inv1 = (lrun[mt][1] > 0.f) ? 1.f / lrun[mt][1] : 0.f;
        int row0 = b * Ss + q0 + w * 32 + mt * 16 + grp;
        #pragma unroll
        for (int n = 0; n < 8; n++) {
            int col = h * HDIM + n * 8 + 2 * tig;
            uint32_t h0, l0, h1, l1;
            split2(oacc[mt][n][0] * inv0, oacc[mt][n][1] * inv0, h0, l0);
            split2(oacc[mt][n][2] * inv1, oacc[mt][n][3] * inv1, h1, l1);
            *(uint32_t*)&Oh[(size_t)row0 * Dd + col]       = h0;
            *(uint32_t*)&Ol[(size_t)row0 * Dd + col]       = l0;
            *(uint32_t*)&Oh[(size_t)(row0 + 8) * Dd + col] = h1;
            *(uint32_t*)&Ol[(size_t)(row0 + 8) * Dd + col] = l1;
        }
    }
}

// ---------------------------------------------------------------------------
extern "C" void kernel_launch(void* const* d_in, const int* in_sizes, int n_in,
                              void* d_out, int out_size)
{
    const float* gene = (const float*)d_in[0];
    const float* expr = (const float*)d_in[1];
    const float* Mm   = (const float*)d_in[2];
    const float* Wf   = (const float*)d_in[3];
    const float* bf   = (const float*)d_in[4];
    const float* Wq   = (const float*)d_in[5];
    const float* bq   = (const float*)d_in[6];
    const float* Wk   = (const float*)d_in[7];
    const float* bk   = (const float*)d_in[8];
    const float* Wv   = (const float*)d_in[9];
    const float* bv   = (const float*)d_in[10];
    const float* Wo   = (const float*)d_in[11];
    const float* bo   = (const float*)d_in[12];
    float* out = (float*)d_out;

    uint16_t *geneh, *genel, *exprh, *exprl, *fush, *fusl;
    uint16_t *qh, *ql, *kh, *kl, *vh, *vl, *ath, *atl;
    uint16_t *wtfh, *wtfl, *wtqkvh, *wtqkvl, *wtoh, *wtol;
    uint32_t* mbits;
    cudaGetSymbolAddress((void**)&geneh, g_gene_h);  cudaGetSymbolAddress((void**)&genel, g_gene_l);
    cudaGetSymbolAddress((void**)&exprh, g_expr_h);  cudaGetSymbolAddress((void**)&exprl, g_expr_l);
    cudaGetSymbolAddress((void**)&fush,  g_fus_h);   cudaGetSymbolAddress((void**)&fusl,  g_fus_l);
    cudaGetSymbolAddress((void**)&qh,    g_q_h);     cudaGetSymbolAddress((void**)&ql,    g_q_l);
    cudaGetSymbolAddress((void**)&kh,    g_k_h);     cudaGetSymbolAddress((void**)&kl,    g_k_l);
    cudaGetSymbolAddress((void**)&vh,    g_v_h);     cudaGetSymbolAddress((void**)&vl,    g_v_l);
    cudaGetSymbolAddress((void**)&ath,   g_at_h);    cudaGetSymbolAddress((void**)&atl,   g_at_l);
    cudaGetSymbolAddress((void**)&wtfh,  g_wtf_h);   cudaGetSymbolAddress((void**)&wtfl,  g_wtf_l);
    cudaGetSymbolAddress((void**)&wtqkvh, g_wtqkv_h); cudaGetSymbolAddress((void**)&wtqkvl, g_wtqkv_l);
    cudaGetSymbolAddress((void**)&wtoh,  g_wto_h);   cudaGetSymbolAddress((void**)&wtol,  g_wto_l);
    cudaGetSymbolAddress((void**)&mbits, g_mbits);

    const int SMG = 2 * G_STG * 2;            // 81920 B
    const int SMF = (3 * F_STG + 128 * FSTR) * 2;  // 73728 B
    cudaFuncSetAttribute(gemm_tc, cudaFuncAttributeMaxDynamicSharedMemorySize, SMG);
    cudaFuncSetAttribute(flash_bf3_kernel, cudaFuncAttributeMaxDynamicSharedMemorySize, SMF);

    const int NE = Bb * Ss * Dd;
    // launch 0: mask bitfield
    maskbits_kernel<<<(Bb * Ss * Ss) / 256, 256>>>(Mm, mbits);
    // launch 1: split gene+expr
    split_kernel<<<dim3(NE / 1024, 2), 256>>>(gene, geneh, genel, expr, exprh, exprl);
    // launch 2: all weight transposes
    transpose_all_kernel<<<dim3(16, 96), 256>>>(Wf, Wq, Wk, Wv, Wo,
                                                wtfh, wtfl, wtqkvh, wtqkvl, wtoh, wtol);

    const int MR = Bb * Ss;                   // 4096
    // launch 3: fused = [gene; expr] @ Wf + bf   (K=1024, N=512)
    gemm_tc<<<dim3(4, MR / 128), 128, SMG>>>(
        geneh, genel, exprh, exprl, nullptr, nullptr, wtfh, wtfl,
        bf, bf, bf, nullptr, fush, fusl, nullptr, nullptr, nullptr, nullptr,
        2 * Dd, 1.f);
    // launch 4: merged QKV (N=1536): seg0 Q (xSCALE, A=fused), seg1 K (A=fused), seg2 V (A=expr)
    gemm_tc<<<dim3(12, MR / 128), 128, SMG>>>(
        fush, fusl, fush, fusl, exprh, exprl, wtqkvh, wtqkvl,
        bq, bk, bv, nullptr, qh, ql, kh, kl, vh, vl,
        Dd, SCALE);
    // launch 5: flash attention (ncu -s 5 captures this one)
    flash_bf3_kernel<<<dim3(Ss / 128, Bb * Hh), 128, SMF>>>(
        qh, ql, kh, kl, vh, vl, mbits, ath, atl);
    // launch 6: output projection -> f32 d_out
    gemm_tc<<<dim3(4, MR / 128), 128, SMG>>>(
        ath, atl, ath, atl, nullptr, nullptr, wtoh, wtol,
        bo, bo, bo, out, nullptr, nullptr, nullptr, nullptr, nullptr, nullptr,
        Dd, 1.f);
}